// round 4
// baseline (speedup 1.0000x reference)
#include <cuda_runtime.h>
#include <cstddef>

#define NCTA 296
#define NTHR 128
#define GT (NCTA * NTHR)
typedef unsigned long long u64;

// ---------------- device scratch (module globals; allocation-free) ----------------
__device__ float g_Xpre[(size_t)512 * 64 * 3072];  // [t][b][3072] layer-0 x-projection
__device__ float g_H2[(size_t)512 * 64 * 1024];    // [t][b][1024] layer-2 h history
__device__ float g_hbuf[2][3][64 * 1024];          // double-buffered h per layer
__device__ float g_z[3][64 * 1024];                // z gate (wave-local)
__device__ float g_rh[3][64 * 1024];               // r*h (wave-local)
__device__ float g_p1x[8][2][64 * 2048];           // zr x-path partials (layers 1,2)
__device__ float g_p1h[8][3][64 * 2048];           // zr h-path partials
__device__ float g_pgx[8][2][64 * 1024];           // g x-path partials (layers 1,2)
__device__ float g_pgh[32][3][64 * 1024];          // g rh-path partials
__device__ unsigned g_cnt;
__device__ volatile unsigned g_gen;

// ---------------- helpers ----------------
__device__ __forceinline__ u64 ffma2(u64 a, u64 b, u64 c) {
    u64 d;
    asm("fma.rn.f32x2 %0, %1, %2, %3;" : "=l"(d) : "l"(a), "l"(b), "l"(c));
    return d;
}
__device__ __forceinline__ float psum(u64 a) {
    float2 f = *reinterpret_cast<float2*>(&a);
    return f.x + f.y;
}

__device__ __forceinline__ void gridbar() {
    __syncthreads();
    if (threadIdx.x == 0) {
        unsigned old = g_gen;
        __threadfence();  // release: push my stores to L2
        if (atomicAdd(&g_cnt, 1u) == NCTA - 1) {
            g_cnt = 0;
            __threadfence();
            g_gen = old + 1;
        } else {
            while (g_gen == old) __nanosleep(32);
            __threadfence();  // acquire: invalidate L1 (fence.gpu -> CCTL.IVALL)
        }
    }
    __syncthreads();
}

// ---------------- GEMM core: C[64 x 128] = A[64 x 32*nch] * W[128 rows x 32*nch]^T
// 128 threads: tx in [0,16) (8 cols each), ty in [0,8) (8 rows each).
// smem u64 layout with XOR swizzle (row<<4) + (k8 ^ (row>>3)); double-buffered,
// register-prefetched; one __syncthreads per chunk + one at end.
__device__ __forceinline__ void gemm_tile(const float* __restrict__ A, int lda,
                                          const float* __restrict__ W, int ldw,
                                          float* __restrict__ C, int cld,
                                          const float* __restrict__ bias, int nch,
                                          u64* __restrict__ Sm) {
    const int tid = threadIdx.x, tx = tid & 15, ty = tid >> 4;
    u64 acc[8][8];
#pragma unroll
    for (int i = 0; i < 8; i++)
#pragma unroll
        for (int j = 0; j < 8; j++) acc[i][j] = 0ull;

    u64 rA[8], rB[16];
#pragma unroll
    for (int it = 0; it < 8; it++) {
        int idx = tid + 128 * it, row = idx >> 4, k8 = idx & 15;
        rA[it] = *reinterpret_cast<const u64*>(A + (size_t)row * lda + (k8 << 1));
    }
#pragma unroll
    for (int it = 0; it < 16; it++) {
        int idx = tid + 128 * it, row = idx >> 4, k8 = idx & 15;
        rB[it] = *reinterpret_cast<const u64*>(W + (size_t)row * ldw + (k8 << 1));
    }

    for (int c = 0; c < nch; c++) {
        u64* Ab = Sm + (c & 1) * 3072;
        u64* Bb = Ab + 1024;
#pragma unroll
        for (int it = 0; it < 8; it++) {
            int idx = tid + 128 * it, row = idx >> 4, k8 = idx & 15;
            Ab[(row << 4) + (k8 ^ ((row >> 3) & 15))] = rA[it];
        }
#pragma unroll
        for (int it = 0; it < 16; it++) {
            int idx = tid + 128 * it, row = idx >> 4, k8 = idx & 15;
            Bb[(row << 4) + (k8 ^ ((row >> 3) & 15))] = rB[it];
        }
        __syncthreads();
        if (c + 1 < nch) {
            const float* A2 = A + (c + 1) * 32;
            const float* W2 = W + (c + 1) * 32;
#pragma unroll
            for (int it = 0; it < 8; it++) {
                int idx = tid + 128 * it, row = idx >> 4, k8 = idx & 15;
                rA[it] = *reinterpret_cast<const u64*>(A2 + (size_t)row * lda + (k8 << 1));
            }
#pragma unroll
            for (int it = 0; it < 16; it++) {
                int idx = tid + 128 * it, row = idx >> 4, k8 = idx & 15;
                rB[it] = *reinterpret_cast<const u64*>(W2 + (size_t)row * ldw + (k8 << 1));
            }
        }
#pragma unroll
        for (int k8 = 0; k8 < 16; k8++) {
            u64 a2[8], b2[8];
#pragma unroll
            for (int i = 0; i < 8; i++) a2[i] = Ab[((ty * 8 + i) << 4) + (k8 ^ ty)];
#pragma unroll
            for (int j = 0; j < 8; j++) b2[j] = Bb[((tx * 8 + j) << 4) + (k8 ^ tx)];
#pragma unroll
            for (int i = 0; i < 8; i++)
#pragma unroll
                for (int j = 0; j < 8; j++) acc[i][j] = ffma2(a2[i], b2[j], acc[i][j]);
        }
    }
#pragma unroll
    for (int i = 0; i < 8; i++)
#pragma unroll
        for (int j = 0; j < 8; j++) {
            float v = psum(acc[i][j]);
            if (bias) v += bias[tx * 8 + j];
            C[(size_t)(ty * 8 + i) * cld + tx * 8 + j] = v;
        }
    __syncthreads();  // protect smem reuse by next job
}

// ---------------- kernels ----------------

// Xpre[t][b][n] = x[b][t][:] . Wx0[n][:]   grid (24, 512)
__global__ __launch_bounds__(NTHR, 2) void k_xpre(const float* __restrict__ x,
                                                  const float* __restrict__ Wx0) {
    __shared__ __align__(16) u64 Sm[6144];
    int n0 = blockIdx.x * 128, s = blockIdx.y;
    gemm_tile(x + (size_t)s * 128, 512 * 128, Wx0 + (size_t)n0 * 128, 128,
              g_Xpre + (size_t)s * 64 * 3072 + n0, 3072, nullptr, 4, Sm);
}

// persistent wavefront GRU
__global__ __launch_bounds__(NTHR, 2) void k_gru(const float* __restrict__ Wh0,
                                                 const float* __restrict__ Wxr,
                                                 const float* __restrict__ Whr,
                                                 const float* __restrict__ bh0,
                                                 const float* __restrict__ bhr) {
    __shared__ __align__(16) u64 Sm[6144];
    const int cta = blockIdx.x, tid = threadIdx.x;
    const int gtid = cta * NTHR + tid;

    for (int i = gtid; i < 2 * 3 * 64 * 1024; i += GT) (&g_hbuf[0][0][0])[i] = 0.f;
    gridbar();

    for (int w = 0; w < 514; ++w) {
        const int rd = w & 1, wb = rd ^ 1;

        // ---- P1: 768 jobs = 96 tiles x 8 k-splits (K=128 each)
        // tiles: l0 zr_h 16 | l1: zr_x 16, zr_h 16, g_x 8 | l2: same
        for (int j = cta; j < 768; j += NCTA) {
            int tile = j >> 3, kq = j & 7;
            int l, kind, tt;
            if (tile < 16) { l = 0; kind = 1; tt = tile; }
            else {
                int r = tile - 16;
                l = 1 + r / 40; r %= 40;
                if (r < 16) { kind = 0; tt = r; }
                else if (r < 32) { kind = 1; tt = r - 16; }
                else { kind = 2; tt = r - 32; }
            }
            int t = w - l;
            if (t < 0 || t >= 512) continue;
            int n0 = tt * 128;
            const float* A;
            const float* Wb;
            float* C;
            int cld;
            if (kind == 0) {
                A = g_hbuf[rd][l - 1];
                Wb = Wxr + (size_t)(l - 1) * 3 * 1048576 + (size_t)n0 * 1024;
                C = g_p1x[kq][l - 1] + n0; cld = 2048;
            } else if (kind == 1) {
                A = g_hbuf[rd][l];
                Wb = (l == 0 ? Wh0 : Whr + (size_t)(l - 1) * 3 * 1048576) + (size_t)n0 * 1024;
                C = g_p1h[kq][l] + n0; cld = 2048;
            } else {
                A = g_hbuf[rd][l - 1];
                Wb = Wxr + (size_t)(l - 1) * 3 * 1048576 + (size_t)(2048 + n0) * 1024;
                C = g_pgx[kq][l - 1] + n0; cld = 1024;
            }
            gemm_tile(A + kq * 128, 1024, Wb + kq * 128, 1024, C, cld, nullptr, 4, Sm);
        }
        gridbar();

        // ---- E1: combine -> z, rh
        for (int idx = gtid; idx < 3 * 64 * 2048; idx += GT) {
            int l = idx >> 17, rem = idx & 131071;
            int t = w - l;
            if (t < 0 || t >= 512) continue;
            int b = rem >> 11, n = rem & 2047;
            float v = (l == 0) ? bh0[n] : bhr[(l - 1) * 3072 + n];
#pragma unroll
            for (int kq = 0; kq < 8; kq++) v += g_p1h[kq][l][rem];
            if (l == 0) {
                v += g_Xpre[((size_t)t * 64 + b) * 3072 + n];
            } else {
#pragma unroll
                for (int kq = 0; kq < 8; kq++) v += g_p1x[kq][l - 1][rem];
            }
            float s = 1.f / (1.f + __expf(-v));
            if (n < 1024) {
                g_z[l][b * 1024 + n] = s;
            } else {
                int nn = n - 1024;
                g_rh[l][b * 1024 + nn] = s * g_hbuf[rd][l][b * 1024 + nn];
            }
        }
        gridbar();

        // ---- P2: rh @ Wh_g. 768 jobs = 24 tiles x 32 k-splits (K=32 each)
        for (int j = cta; j < 768; j += NCTA) {
            int tile = j >> 5, kq = j & 31;
            int l = tile >> 3, tt = tile & 7;
            int t = w - l;
            if (t < 0 || t >= 512) continue;
            int n0 = tt * 128;
            const float* Wb =
                (l == 0 ? Wh0 : Whr + (size_t)(l - 1) * 3 * 1048576) + (size_t)(2048 + n0) * 1024;
            gemm_tile(g_rh[l] + kq * 32, 1024, Wb + kq * 32, 1024,
                      g_pgh[kq][l] + n0, 1024, nullptr, 1, Sm);
        }
        gridbar();

        // ---- E2: combine -> g, update h, emit H2
        for (int idx = gtid; idx < 3 * 64 * 1024; idx += GT) {
            int l = idx >> 16, rem = idx & 65535;
            int t = w - l;
            if (t < 0 || t >= 512) continue;
            int b = rem >> 10, n = rem & 1023;
            float v = (l == 0) ? bh0[2048 + n] : bhr[(l - 1) * 3072 + 2048 + n];
#pragma unroll
            for (int kq = 0; kq < 32; kq++) v += g_pgh[kq][l][rem];
            if (l == 0) {
                v += g_Xpre[((size_t)t * 64 + b) * 3072 + 2048 + n];
            } else {
#pragma unroll
                for (int kq = 0; kq < 8; kq++) v += g_pgx[kq][l - 1][rem];
            }
            float g = tanhf(v);
            float z = g_z[l][rem];
            float hp = g_hbuf[rd][l][rem];
            float hn = z * hp + (1.f - z) * g;
            g_hbuf[wb][l][rem] = hn;
            if (l == 2) g_H2[((size_t)t * 64 + b) * 1024 + n] = hn;
        }
        gridbar();
    }
}

// y[b][s][o] = H2[s][b][:] . Wout[o][:] + bout   grid (512)
__global__ __launch_bounds__(NTHR, 2) void k_yout(const float* __restrict__ Wout,
                                                  const float* __restrict__ bout,
                                                  float* __restrict__ out) {
    __shared__ __align__(16) u64 Sm[6144];
    int s = blockIdx.x;
    gemm_tile(g_H2 + (size_t)s * 64 * 1024, 1024, Wout, 1024,
              out + (size_t)s * 128, 512 * 128, bout, 32, Sm);
}

// hidden_state (B, L, H): layer l's final h sits in parity buffer l&1
__global__ void k_hout(float* __restrict__ out) {
    int i = blockIdx.x * 256 + threadIdx.x;
    if (i >= 3 * 64 * 1024) return;
    int l = i / (64 * 1024);
    int r = i % (64 * 1024);
    int b = r / 1024, n = r % 1024;
    out[(size_t)64 * 512 * 128 + ((size_t)b * 3 + l) * 1024 + n] = g_hbuf[l & 1][l][r];
}

extern "C" void kernel_launch(void* const* d_in, const int* in_sizes, int n_in,
                              void* d_out, int out_size) {
    const float* x = (const float*)d_in[0];
    const float* Wx0 = (const float*)d_in[1];
    const float* Wh0 = (const float*)d_in[2];
    const float* bh0 = (const float*)d_in[3];
    const float* Wxr = (const float*)d_in[4];
    const float* Whr = (const float*)d_in[5];
    const float* bhr = (const float*)d_in[6];
    const float* Wout = (const float*)d_in[7];
    const float* bout = (const float*)d_in[8];
    float* out = (float*)d_out;

    k_xpre<<<dim3(24, 512), NTHR>>>(x, Wx0);
    k_gru<<<NCTA, NTHR>>>(Wh0, Wxr, Whr, bh0, bhr);
    k_yout<<<512, NTHR>>>(Wout, bout, out);
    k_hout<<<(3 * 64 * 1024 + 255) / 256, 256>>>(out);
}

// round 5
// speedup vs baseline: 1.0971x; 1.0971x over previous
#include <cuda_runtime.h>
#include <cstddef>

#define NCTA 296
#define NTHR 128
#define GT (NCTA * NTHR)
typedef unsigned long long u64;

// ---------------- device scratch (module globals; allocation-free) ----------------
__device__ float g_Xpre[(size_t)512 * 64 * 3072];  // [t][b][3072] layer-0 x-projection
__device__ float g_H2[(size_t)512 * 64 * 1024];    // [t][b][1024] layer-2 h history
__device__ float g_hbuf[2][3][64 * 1024];          // double-buffered h per layer
__device__ float g_rh[3][64 * 1024];               // r*h (wave-local)
__device__ float g_p1x[8][2][64 * 2048];           // zr x-path partials (layers 1,2)
__device__ float g_p1h[8][3][64 * 2048];           // zr h-path partials
__device__ float g_pgx[8][2][64 * 1024];           // g x-path partials (layers 1,2)
__device__ float g_pgh[32][3][64 * 1024];          // g rh-path partials
__device__ unsigned g_cnt;
__device__ volatile unsigned g_gen;
__device__ unsigned g_jc[2];                       // steal counters: [0]=P1, [1]=P2

// ---------------- helpers ----------------
__device__ __forceinline__ u64 ffma2(u64 a, u64 b, u64 c) {
    u64 d;
    asm("fma.rn.f32x2 %0, %1, %2, %3;" : "=l"(d) : "l"(a), "l"(b), "l"(c));
    return d;
}
__device__ __forceinline__ float psum(u64 a) {
    float2 f = *reinterpret_cast<float2*>(&a);
    return f.x + f.y;
}
__device__ __forceinline__ float sigm(float x) { return 1.f / (1.f + __expf(-x)); }
__device__ __forceinline__ void add4(float4& a, const float4 b) {
    a.x += b.x; a.y += b.y; a.z += b.z; a.w += b.w;
}

// barrier; master optionally resets a steal counter before releasing
__device__ __forceinline__ void gridbar(int rst) {
    __syncthreads();
    if (threadIdx.x == 0) {
        unsigned old = g_gen;
        __threadfence();  // release: drain my stores
        if (atomicAdd(&g_cnt, 1u) == NCTA - 1) {
            g_cnt = 0;
            if (rst >= 0) g_jc[rst] = 0;
            __threadfence();
            g_gen = old + 1;
        } else {
            while (g_gen == old) __nanosleep(32);
            __threadfence();  // acquire
        }
    }
    __syncthreads();
}

// ---------------- GEMM core: C[64 x 128] = A[64 x 32*nch] * W[128 rows x 32*nch]^T
__device__ __forceinline__ void gemm_tile(const float* __restrict__ A, int lda,
                                          const float* __restrict__ W, int ldw,
                                          float* __restrict__ C, int cld,
                                          const float* __restrict__ bias, int nch,
                                          u64* __restrict__ Sm) {
    const int tid = threadIdx.x, tx = tid & 15, ty = tid >> 4;
    u64 acc[8][8];
#pragma unroll
    for (int i = 0; i < 8; i++)
#pragma unroll
        for (int j = 0; j < 8; j++) acc[i][j] = 0ull;

    u64 rA[8], rB[16];
#pragma unroll
    for (int it = 0; it < 8; it++) {
        int idx = tid + 128 * it, row = idx >> 4, k8 = idx & 15;
        rA[it] = *reinterpret_cast<const u64*>(A + (size_t)row * lda + (k8 << 1));
    }
#pragma unroll
    for (int it = 0; it < 16; it++) {
        int idx = tid + 128 * it, row = idx >> 4, k8 = idx & 15;
        rB[it] = *reinterpret_cast<const u64*>(W + (size_t)row * ldw + (k8 << 1));
    }

    for (int c = 0; c < nch; c++) {
        u64* Ab = Sm + (c & 1) * 3072;
        u64* Bb = Ab + 1024;
#pragma unroll
        for (int it = 0; it < 8; it++) {
            int idx = tid + 128 * it, row = idx >> 4, k8 = idx & 15;
            Ab[(row << 4) + (k8 ^ ((row >> 3) & 15))] = rA[it];
        }
#pragma unroll
        for (int it = 0; it < 16; it++) {
            int idx = tid + 128 * it, row = idx >> 4, k8 = idx & 15;
            Bb[(row << 4) + (k8 ^ ((row >> 3) & 15))] = rB[it];
        }
        __syncthreads();
        if (c + 1 < nch) {
            const float* A2 = A + (c + 1) * 32;
            const float* W2 = W + (c + 1) * 32;
#pragma unroll
            for (int it = 0; it < 8; it++) {
                int idx = tid + 128 * it, row = idx >> 4, k8 = idx & 15;
                rA[it] = *reinterpret_cast<const u64*>(A2 + (size_t)row * lda + (k8 << 1));
            }
#pragma unroll
            for (int it = 0; it < 16; it++) {
                int idx = tid + 128 * it, row = idx >> 4, k8 = idx & 15;
                rB[it] = *reinterpret_cast<const u64*>(W2 + (size_t)row * ldw + (k8 << 1));
            }
        }
#pragma unroll
        for (int k8 = 0; k8 < 16; k8++) {
            u64 a2[8], b2[8];
#pragma unroll
            for (int i = 0; i < 8; i++) a2[i] = Ab[((ty * 8 + i) << 4) + (k8 ^ ty)];
#pragma unroll
            for (int j = 0; j < 8; j++) b2[j] = Bb[((tx * 8 + j) << 4) + (k8 ^ tx)];
#pragma unroll
            for (int i = 0; i < 8; i++)
#pragma unroll
                for (int j = 0; j < 8; j++) acc[i][j] = ffma2(a2[i], b2[j], acc[i][j]);
        }
    }
#pragma unroll
    for (int i = 0; i < 8; i++)
#pragma unroll
        for (int j = 0; j < 8; j++) {
            float v = psum(acc[i][j]);
            if (bias) v += bias[tx * 8 + j];
            C[(size_t)(ty * 8 + i) * cld + tx * 8 + j] = v;
        }
    __syncthreads();
}

// ---------------- kernels ----------------
__global__ void k_pad() {}

// Xpre[t][b][n] = x[b][t][:] . Wx0[n][:]   grid (24, 512)
__global__ __launch_bounds__(NTHR, 2) void k_xpre(const float* __restrict__ x,
                                                  const float* __restrict__ Wx0) {
    __shared__ __align__(16) u64 Sm[6144];
    int n0 = blockIdx.x * 128, s = blockIdx.y;
    gemm_tile(x + (size_t)s * 128, 512 * 128, Wx0 + (size_t)n0 * 128, 128,
              g_Xpre + (size_t)s * 64 * 3072 + n0, 3072, nullptr, 4, Sm);
}

// persistent wavefront GRU
__global__ __launch_bounds__(NTHR, 2) void k_gru(const float* __restrict__ Wh0,
                                                 const float* __restrict__ Wxr,
                                                 const float* __restrict__ Whr,
                                                 const float* __restrict__ bh0,
                                                 const float* __restrict__ bhr) {
    __shared__ __align__(16) u64 Sm[6144];
    __shared__ int sj;
    const int tid = threadIdx.x;
    const int gtid = blockIdx.x * NTHR + tid;

    for (int i = gtid; i < 2 * 3 * 64 * 1024; i += GT) (&g_hbuf[0][0][0])[i] = 0.f;
    gridbar(0);  // also resets P1 counter

    for (int w = 0; w < 514; ++w) {
        const int rd = w & 1, wb = rd ^ 1;

        // ---- P1 (steal): 768 jobs = 96 tiles x 8 k-splits (K=128 each)
        while (true) {
            if (tid == 0) sj = (int)atomicAdd(&g_jc[0], 1u);
            __syncthreads();
            int j = sj;
            __syncthreads();
            if (j >= 768) break;
            int tile = j >> 3, kq = j & 7;
            int l, kind, tt;
            if (tile < 16) { l = 0; kind = 1; tt = tile; }
            else {
                int r = tile - 16;
                l = 1 + r / 40; r %= 40;
                if (r < 16) { kind = 0; tt = r; }
                else if (r < 32) { kind = 1; tt = r - 16; }
                else { kind = 2; tt = r - 32; }
            }
            int t = w - l;
            if (t < 0 || t >= 512) continue;
            int n0 = tt * 128;
            const float* A;
            const float* Wb;
            float* C;
            int cld;
            if (kind == 0) {
                A = g_hbuf[rd][l - 1];
                Wb = Wxr + (size_t)(l - 1) * 3 * 1048576 + (size_t)n0 * 1024;
                C = g_p1x[kq][l - 1] + n0; cld = 2048;
            } else if (kind == 1) {
                A = g_hbuf[rd][l];
                Wb = (l == 0 ? Wh0 : Whr + (size_t)(l - 1) * 3 * 1048576) + (size_t)n0 * 1024;
                C = g_p1h[kq][l] + n0; cld = 2048;
            } else {
                A = g_hbuf[rd][l - 1];
                Wb = Wxr + (size_t)(l - 1) * 3 * 1048576 + (size_t)(2048 + n0) * 1024;
                C = g_pgx[kq][l - 1] + n0; cld = 1024;
            }
            gemm_tile(A + kq * 128, 1024, Wb + kq * 128, 1024, C, cld, nullptr, 4, Sm);
        }
        gridbar(1);  // reset P2 counter

        // ---- E1: rh only (float4). 49152 groups = 3 layers x 64 b x 256 n4
        for (int g4 = gtid; g4 < 49152; g4 += GT) {
            int l = g4 >> 14, rem = g4 & 16383;
            int t = w - l;
            if (t < 0 || t >= 512) continue;
            int b = rem >> 8, n = (rem & 255) << 2;
            const float* bias = (l == 0) ? bh0 : bhr + (l - 1) * 3072;
            float4 v = *reinterpret_cast<const float4*>(bias + 1024 + n);
            int off = b * 2048 + 1024 + n;
#pragma unroll
            for (int kq = 0; kq < 8; kq++)
                add4(v, *reinterpret_cast<const float4*>(&g_p1h[kq][l][off]));
            if (l == 0) {
                add4(v, *reinterpret_cast<const float4*>(
                            &g_Xpre[((size_t)t * 64 + b) * 3072 + 1024 + n]));
            } else {
#pragma unroll
                for (int kq = 0; kq < 8; kq++)
                    add4(v, *reinterpret_cast<const float4*>(&g_p1x[kq][l - 1][off]));
            }
            float4 hp = *reinterpret_cast<const float4*>(&g_hbuf[rd][l][b * 1024 + n]);
            float4 r;
            r.x = sigm(v.x) * hp.x; r.y = sigm(v.y) * hp.y;
            r.z = sigm(v.z) * hp.z; r.w = sigm(v.w) * hp.w;
            *reinterpret_cast<float4*>(&g_rh[l][b * 1024 + n]) = r;
        }
        gridbar(-1);

        // ---- P2 (steal): rh @ Wh_g. 768 jobs = 24 tiles x 32 k-splits (K=32)
        while (true) {
            if (tid == 0) sj = (int)atomicAdd(&g_jc[1], 1u);
            __syncthreads();
            int j = sj;
            __syncthreads();
            if (j >= 768) break;
            int tile = j >> 5, kq = j & 31;
            int l = tile >> 3, tt = tile & 7;
            int t = w - l;
            if (t < 0 || t >= 512) continue;
            int n0 = tt * 128;
            const float* Wb =
                (l == 0 ? Wh0 : Whr + (size_t)(l - 1) * 3 * 1048576) + (size_t)(2048 + n0) * 1024;
            gemm_tile(g_rh[l] + kq * 32, 1024, Wb + kq * 32, 1024,
                      g_pgh[kq][l] + n0, 1024, nullptr, 1, Sm);
        }
        gridbar(-1);

        // ---- E2: z + g + h update (float4). 49152 groups
        for (int g4 = gtid; g4 < 49152; g4 += GT) {
            int l = g4 >> 14, rem = g4 & 16383;
            int t = w - l;
            if (t < 0 || t >= 512) continue;
            int b = rem >> 8, n = (rem & 255) << 2;
            const float* bias = (l == 0) ? bh0 : bhr + (l - 1) * 3072;
            int offz = b * 2048 + n;
            int offg = b * 1024 + n;
            float4 vz = *reinterpret_cast<const float4*>(bias + n);
            float4 vg = *reinterpret_cast<const float4*>(bias + 2048 + n);
#pragma unroll
            for (int kq = 0; kq < 8; kq++)
                add4(vz, *reinterpret_cast<const float4*>(&g_p1h[kq][l][offz]));
#pragma unroll
            for (int kq = 0; kq < 32; kq++)
                add4(vg, *reinterpret_cast<const float4*>(&g_pgh[kq][l][offg]));
            if (l == 0) {
                const float* xp = &g_Xpre[((size_t)t * 64 + b) * 3072];
                add4(vz, *reinterpret_cast<const float4*>(xp + n));
                add4(vg, *reinterpret_cast<const float4*>(xp + 2048 + n));
            } else {
#pragma unroll
                for (int kq = 0; kq < 8; kq++)
                    add4(vz, *reinterpret_cast<const float4*>(&g_p1x[kq][l - 1][offz]));
#pragma unroll
                for (int kq = 0; kq < 8; kq++)
                    add4(vg, *reinterpret_cast<const float4*>(&g_pgx[kq][l - 1][offg]));
            }
            float4 hp = *reinterpret_cast<const float4*>(&g_hbuf[rd][l][offg]);
            float4 hn;
            {
                float z0 = sigm(vz.x), z1 = sigm(vz.y), z2 = sigm(vz.z), z3 = sigm(vz.w);
                hn.x = z0 * hp.x + (1.f - z0) * tanhf(vg.x);
                hn.y = z1 * hp.y + (1.f - z1) * tanhf(vg.y);
                hn.z = z2 * hp.z + (1.f - z2) * tanhf(vg.z);
                hn.w = z3 * hp.w + (1.f - z3) * tanhf(vg.w);
            }
            *reinterpret_cast<float4*>(&g_hbuf[wb][l][offg]) = hn;
            if (l == 2)
                *reinterpret_cast<float4*>(&g_H2[((size_t)t * 64 + b) * 1024 + n]) = hn;
        }
        gridbar(0);  // reset P1 counter for next wave
    }
}

// y[b][s][o] = H2[s][b][:] . Wout[o][:] + bout   grid (512)
__global__ __launch_bounds__(NTHR, 2) void k_yout(const float* __restrict__ Wout,
                                                  const float* __restrict__ bout,
                                                  float* __restrict__ out) {
    __shared__ __align__(16) u64 Sm[6144];
    int s = blockIdx.x;
    gemm_tile(g_H2 + (size_t)s * 64 * 1024, 1024, Wout, 1024,
              out + (size_t)s * 128, 512 * 128, bout, 32, Sm);
}

// hidden_state (B, L, H): layer l's final h sits in parity buffer l&1
__global__ void k_hout(float* __restrict__ out) {
    int i = blockIdx.x * 256 + threadIdx.x;
    if (i >= 3 * 64 * 1024) return;
    int l = i / (64 * 1024);
    int r = i % (64 * 1024);
    int b = r / 1024, n = r % 1024;
    out[(size_t)64 * 512 * 128 + ((size_t)b * 3 + l) * 1024 + n] = g_hbuf[l & 1][l][r];
}

extern "C" void kernel_launch(void* const* d_in, const int* in_sizes, int n_in,
                              void* d_out, int out_size) {
    const float* x = (const float*)d_in[0];
    const float* Wx0 = (const float*)d_in[1];
    const float* Wh0 = (const float*)d_in[2];
    const float* bh0 = (const float*)d_in[3];
    const float* Wxr = (const float*)d_in[4];
    const float* Whr = (const float*)d_in[5];
    const float* bhr = (const float*)d_in[6];
    const float* Wout = (const float*)d_in[7];
    const float* bout = (const float*)d_in[8];
    float* out = (float*)d_out;

    k_pad<<<1, 32>>>();
    k_pad<<<1, 32>>>();
    k_xpre<<<dim3(24, 512), NTHR>>>(x, Wx0);
    k_gru<<<NCTA, NTHR>>>(Wh0, Wxr, Whr, bh0, bhr);
    k_yout<<<512, NTHR>>>(Wout, bout, out);
    k_hout<<<(3 * 64 * 1024 + 255) / 256, 256>>>(out);
}